// round 14
// baseline (speedup 1.0000x reference)
#include <cuda_runtime.h>
#include <cuda_bf16.h>
#include <math.h>

#define IN_C  128
#define HID_C 64
#define OUT_C 32
#define NMAX  100096
#define EMAX  1600512
#define SCAN_BLK 1024

// ---------------- scratch (device globals) ----------------------------------
__device__ int   g_is64;
__device__ __align__(16) int   g_esrc  [EMAX];
__device__ __align__(16) int   g_cnt   [NMAX];
__device__ __align__(16) int   g_rowptr[NMAX];
__device__ __align__(16) int   g_cursor[NMAX];
__device__ __align__(16) int   g_bsum  [SCAN_BLK];
__device__ __align__(16) float g_dinv  [NMAX];
__device__ __align__(16) float g_h1pre [NMAX * HID_C];
__device__ __align__(16) float g_agg1  [NMAX * HID_C];
__device__ __align__(16) float g_h2pre [NMAX * OUT_C];
__device__ __align__(16) float g_agg2  [NMAX * OUT_C];
__device__ __align__(16) float g_pfin  [NMAX * OUT_C];   // x @ Wl[0:128]

// ---------------- dtype detect ----------------------------------------------
__global__ void detect_kernel(const void* ei, int n) {
    const long long* p = (const long long*)ei;
    int ok = 1;
#pragma unroll
    for (int i = 0; i < 16; i++) {
        long long v = p[i];
        if (v < 0 || v >= (long long)n) ok = 0;
    }
    g_is64 = ok;
}

__global__ void count_kernel(const void* ei, int E, int n) {
    int i = blockIdx.x * blockDim.x + threadIdx.x;
    if (i >= E) return;
    int d;
    if (g_is64) d = (int)((const long long*)ei)[E + i];
    else        d = ((const int*)ei)[E + i];
    d = (unsigned)d < (unsigned)n ? d : 0;
    atomicAdd(&g_cnt[d], 1);
}

__global__ void dinv_kernel(int n) {
    int i = blockIdx.x * blockDim.x + threadIdx.x;
    if (i < n) g_dinv[i] = rsqrtf((float)g_cnt[i] + 1.0f);
}

// ---------------- scan of g_cnt -> g_rowptr ---------------------------------
__global__ void scan1_kernel(int n) {
    __shared__ int sm[SCAN_BLK];
    int tid = threadIdx.x;
    int gi = blockIdx.x * SCAN_BLK + tid;
    int v = (gi < n) ? g_cnt[gi] : 0;
    sm[tid] = v;
    __syncthreads();
    for (int off = 1; off < SCAN_BLK; off <<= 1) {
        int t = (tid >= off) ? sm[tid - off] : 0;
        __syncthreads();
        sm[tid] += t;
        __syncthreads();
    }
    if (gi < n) g_rowptr[gi] = sm[tid];
    if (tid == SCAN_BLK - 1) g_bsum[blockIdx.x] = sm[tid];
}
__global__ void scan2_kernel(int nblocks) {
    __shared__ int sm[SCAN_BLK];
    int tid = threadIdx.x;
    int v = (tid < nblocks) ? g_bsum[tid] : 0;
    sm[tid] = v;
    __syncthreads();
    for (int off = 1; off < SCAN_BLK; off <<= 1) {
        int t = (tid >= off) ? sm[tid - off] : 0;
        __syncthreads();
        sm[tid] += t;
        __syncthreads();
    }
    if (tid < nblocks) g_bsum[tid] = sm[tid] - v;
}
__global__ void scan3_kernel(int n) {
    int gi = blockIdx.x * SCAN_BLK + threadIdx.x;
    if (gi < n) {
        int r = g_rowptr[gi] - g_cnt[gi] + g_bsum[blockIdx.x];
        g_rowptr[gi] = r;
        g_cursor[gi] = r;
    }
}

__global__ void fill_kernel(const void* ei, int E, int n) {
    int e = blockIdx.x * blockDim.x + threadIdx.x;
    if (e >= E) return;
    int s, d;
    if (g_is64) {
        const long long* p = (const long long*)ei;
        s = (int)p[e];
        d = (int)p[E + e];
    } else {
        const int* p = (const int*)ei;
        s = p[e];
        d = p[E + e];
    }
    s = (unsigned)s < (unsigned)n ? s : 0;
    d = (unsigned)d < (unsigned)n ? d : 0;
    int pos = atomicAdd(&g_cursor[d], 1);
    g_esrc[pos] = s;
}

// ---------------- tiled SGEMM: C[M,BN] = A[M,K] @ B[K,BN] -------------------
template <int BM, int BN, int BK, int TM, int TN, int K>
__global__ void sgemm_kernel(const float* __restrict__ A,
                             const float* __restrict__ B,
                             float* __restrict__ C, int M) {
    constexpr int THREADS = (BM / TM) * (BN / TN);
    __shared__ float As[BK][BM];
    __shared__ float Bs[BK][BN];

    const int tid = threadIdx.x;
    const int tx = tid % (BN / TN);
    const int ty = tid / (BN / TN);
    const int rowBase = blockIdx.x * BM;

    float acc[TM][TN];
#pragma unroll
    for (int i = 0; i < TM; i++)
#pragma unroll
        for (int j = 0; j < TN; j++) acc[i][j] = 0.f;

    for (int kt = 0; kt < K; kt += BK) {
        constexpr int A_LD4 = BM * BK / 4;
#pragma unroll
        for (int i = tid; i < A_LD4; i += THREADS) {
            int idx = i * 4;
            int r = idx / BK;
            int c = idx % BK;
            int grow = rowBase + r;
            float4 v = (grow < M) ? *(const float4*)(A + (size_t)grow * K + kt + c)
                                  : make_float4(0.f, 0.f, 0.f, 0.f);
            As[c + 0][r] = v.x; As[c + 1][r] = v.y;
            As[c + 2][r] = v.z; As[c + 3][r] = v.w;
        }
        constexpr int B_LD4 = BK * BN / 4;
#pragma unroll
        for (int i = tid; i < B_LD4; i += THREADS) {
            int idx = i * 4;
            int r = idx / BN;
            int c = idx % BN;
            *(float4*)(&Bs[r][c]) = *(const float4*)(B + (size_t)(kt + r) * BN + c);
        }
        __syncthreads();

#pragma unroll
        for (int k = 0; k < BK; k++) {
            float ra[TM], rb[TN];
#pragma unroll
            for (int i = 0; i < TM; i += 4)
                *(float4*)&ra[i] = *(const float4*)&As[k][ty * TM + i];
            if (TN == 4)      *(float4*)&rb[0] = *(const float4*)&Bs[k][tx * TN];
            else if (TN == 2) *(float2*)&rb[0] = *(const float2*)&Bs[k][tx * TN];
#pragma unroll
            for (int i = 0; i < TM; i++)
#pragma unroll
                for (int j = 0; j < TN; j++) acc[i][j] += ra[i] * rb[j];
        }
        __syncthreads();
    }

#pragma unroll
    for (int i = 0; i < TM; i++) {
        int grow = rowBase + ty * TM + i;
        if (grow < M) {
            if (TN == 4)
                *(float4*)(C + (size_t)grow * BN + tx * TN) = *(float4*)&acc[i][0];
            else if (TN == 2)
                *(float2*)(C + (size_t)grow * BN + tx * TN) = *(float2*)&acc[i][0];
        }
    }
}

// ---------------- CSR gathers: prefetch+shfl broadcast ----------------------
// layer 1: warp per node, lane owns float2 channels {2*lane, 2*lane+1}
__global__ void gather1_kernel(const float* __restrict__ b1, int n) {
    int warp = threadIdx.x >> 5;
    int lane = threadIdx.x & 31;
    int node = blockIdx.x * 8 + warp;
    if (node >= n) return;

    int start = g_rowptr[node];
    int cnt   = g_cnt[node];
    float dd  = g_dinv[node];

    const float2* __restrict__ h = (const float2*)g_h1pre;   // 32 float2/row
    float ax = 0.f, ay = 0.f;

    for (int base = 0; base < cnt; base += 32) {
        int rem = cnt - base; if (rem > 32) rem = 32;
        int  s  = 0; float ds = 0.f;
        if (lane < rem) {
            s  = g_esrc[start + base + lane];
            ds = g_dinv[s];
        }
        int j = 0;
        for (; j + 4 <= rem; j += 4) {
#pragma unroll
            for (int u = 0; u < 4; u++) {
                int   sj = __shfl_sync(0xffffffffu, s,  j + u);
                float nj = __shfl_sync(0xffffffffu, ds, j + u) * dd;
                float2 v = h[(size_t)sj * 32 + lane];
                ax += v.x * nj;
                ay += v.y * nj;
            }
        }
        for (; j < rem; j++) {
            int   sj = __shfl_sync(0xffffffffu, s,  j);
            float nj = __shfl_sync(0xffffffffu, ds, j) * dd;
            float2 v = h[(size_t)sj * 32 + lane];
            ax += v.x * nj;
            ay += v.y * nj;
        }
    }

    float d2 = dd * dd;
    float2 hn = h[(size_t)node * 32 + lane];
    float2 bb = ((const float2*)b1)[lane];
    float2 o;
    o.x = fmaxf(ax + hn.x * d2 + bb.x, 0.f);
    o.y = fmaxf(ay + hn.y * d2 + bb.y, 0.f);
    ((float2*)g_agg1)[(size_t)node * 32 + lane] = o;
}

// layer 2: warp per node, lane owns 1 channel
__global__ void gather2_kernel(const float* __restrict__ b2, int n) {
    int warp = threadIdx.x >> 5;
    int lane = threadIdx.x & 31;
    int node = blockIdx.x * 8 + warp;
    if (node >= n) return;

    int start = g_rowptr[node];
    int cnt   = g_cnt[node];
    float dd  = g_dinv[node];

    const float* __restrict__ h = g_h2pre;
    float a0 = 0.f;

    for (int base = 0; base < cnt; base += 32) {
        int rem = cnt - base; if (rem > 32) rem = 32;
        int  s  = 0; float ds = 0.f;
        if (lane < rem) {
            s  = g_esrc[start + base + lane];
            ds = g_dinv[s];
        }
        int j = 0;
        for (; j + 4 <= rem; j += 4) {
#pragma unroll
            for (int u = 0; u < 4; u++) {
                int   sj = __shfl_sync(0xffffffffu, s,  j + u);
                float nj = __shfl_sync(0xffffffffu, ds, j + u) * dd;
                a0 += h[(size_t)sj * OUT_C + lane] * nj;
            }
        }
        for (; j < rem; j++) {
            int   sj = __shfl_sync(0xffffffffu, s,  j);
            float nj = __shfl_sync(0xffffffffu, ds, j) * dd;
            a0 += h[(size_t)sj * OUT_C + lane] * nj;
        }
    }

    float d2 = dd * dd;
    g_agg2[(size_t)node * OUT_C + lane] =
        a0 + h[(size_t)node * OUT_C + lane] * d2 + b2[lane];
}

// ---------------- final2: out = pfin + [h1,h2] @ Wl[128:224] + bl -> lsm ----
// 256 threads, 128 rows/block; thread (ty=tid/8, tx=tid%8) -> 4 rows x 4 cols.
__global__ void final2_kernel(const float* __restrict__ Wl,
                              const float* __restrict__ bl,
                              float* __restrict__ out, int n) {
    __shared__ float WsT[32][100];   // WsT[c][k] = Wl[(128+k)*32 + c], k<96
    const int tid = threadIdx.x;
    for (int i = tid; i < 32 * 96; i += 256) {
        int c = i / 96;
        int k = i % 96;
        WsT[c][k] = Wl[(128 + k) * OUT_C + c];
    }
    __syncthreads();

    const int ty = tid >> 3;          // 0..31
    const int tx = tid & 7;           // 0..7
    const int rowBase = blockIdx.x * 128 + ty * 4;

    float acc[4][4];
#pragma unroll
    for (int i = 0; i < 4; i++)
#pragma unroll
        for (int j = 0; j < 4; j++) acc[i][j] = 0.f;

    const float4 zero4 = make_float4(0.f, 0.f, 0.f, 0.f);

    // segment 1: k = 0..63 from agg1 (h1)
#pragma unroll
    for (int k4 = 0; k4 < 16; k4++) {
        float4 ra[4];
#pragma unroll
        for (int i = 0; i < 4; i++) {
            int row = rowBase + i;
            ra[i] = (row < n) ? *(const float4*)(g_agg1 + (size_t)row * HID_C + k4 * 4)
                              : zero4;
        }
#pragma unroll
        for (int j = 0; j < 4; j++) {
            float4 rb = *(const float4*)&WsT[tx * 4 + j][k4 * 4];
#pragma unroll
            for (int i = 0; i < 4; i++)
                acc[i][j] += ra[i].x * rb.x + ra[i].y * rb.y
                           + ra[i].z * rb.z + ra[i].w * rb.w;
        }
    }
    // segment 2: k = 64..95 from agg2 (h2)
#pragma unroll
    for (int k4 = 0; k4 < 8; k4++) {
        float4 ra[4];
#pragma unroll
        for (int i = 0; i < 4; i++) {
            int row = rowBase + i;
            ra[i] = (row < n) ? *(const float4*)(g_agg2 + (size_t)row * OUT_C + k4 * 4)
                              : zero4;
        }
#pragma unroll
        for (int j = 0; j < 4; j++) {
            float4 rb = *(const float4*)&WsT[tx * 4 + j][64 + k4 * 4];
#pragma unroll
            for (int i = 0; i < 4; i++)
                acc[i][j] += ra[i].x * rb.x + ra[i].y * rb.y
                           + ra[i].z * rb.z + ra[i].w * rb.w;
        }
    }

    float4 bb = *(const float4*)(bl + tx * 4);

#pragma unroll
    for (int i = 0; i < 4; i++) {
        int row = rowBase + i;
        float4 pf = (row < n) ? *(const float4*)(g_pfin + (size_t)row * OUT_C + tx * 4)
                              : zero4;
        float l0 = acc[i][0] + pf.x + bb.x;
        float l1 = acc[i][1] + pf.y + bb.y;
        float l2 = acc[i][2] + pf.z + bb.z;
        float l3 = acc[i][3] + pf.w + bb.w;
        float m = fmaxf(fmaxf(l0, l1), fmaxf(l2, l3));
        m = fmaxf(m, __shfl_xor_sync(0xffffffffu, m, 1));
        m = fmaxf(m, __shfl_xor_sync(0xffffffffu, m, 2));
        m = fmaxf(m, __shfl_xor_sync(0xffffffffu, m, 4));
        float s = __expf(l0 - m) + __expf(l1 - m) + __expf(l2 - m) + __expf(l3 - m);
        s += __shfl_xor_sync(0xffffffffu, s, 1);
        s += __shfl_xor_sync(0xffffffffu, s, 2);
        s += __shfl_xor_sync(0xffffffffu, s, 4);
        float ls = m + __logf(s);
        if (row < n) {
            float4 o = make_float4(l0 - ls, l1 - ls, l2 - ls, l3 - ls);
            *(float4*)(out + (size_t)row * OUT_C + tx * 4) = o;
        }
    }
}

// ---------------- launch ----------------------------------------------------
extern "C" void kernel_launch(void* const* d_in, const int* in_sizes, int n_in,
                              void* d_out, int out_size) {
    const float* x  = (const float*)d_in[0];
    const void*  ei = d_in[1];
    const float* W1 = (const float*)d_in[2];
    const float* b1 = (const float*)d_in[3];
    const float* W2 = (const float*)d_in[4];
    const float* b2 = (const float*)d_in[5];
    const float* Wl = (const float*)d_in[6];
    const float* bl = (const float*)d_in[7];
    float* out = (float*)d_out;

    const int n = in_sizes[0] / IN_C;
    const int E = in_sizes[1] / 2;

    int* cnt;
    float *h1pre, *agg1, *h2pre, *pfin;
    cudaGetSymbolAddress((void**)&cnt,   g_cnt);
    cudaGetSymbolAddress((void**)&h1pre, g_h1pre);
    cudaGetSymbolAddress((void**)&agg1,  g_agg1);
    cudaGetSymbolAddress((void**)&h2pre, g_h2pre);
    cudaGetSymbolAddress((void**)&pfin,  g_pfin);

    static cudaStream_t s2 = nullptr;
    static cudaEvent_t evFork = nullptr, evJoin = nullptr;
    if (s2 == nullptr) {
        cudaStreamCreateWithFlags(&s2, cudaStreamNonBlocking);
        cudaEventCreateWithFlags(&evFork, cudaEventDisableTiming);
        cudaEventCreateWithFlags(&evJoin, cudaEventDisableTiming);
    }

    const int T = 256;
    const int nScanBlocks = (n + SCAN_BLK - 1) / SCAN_BLK;

    // ---- fork: CSR preprocessing + x@Wl partial on s2
    cudaEventRecord(evFork, 0);
    cudaStreamWaitEvent(s2, evFork, 0);

    detect_kernel<<<1, 1, 0, s2>>>(ei, n);
    cudaMemsetAsync(cnt, 0, (size_t)n * sizeof(int), s2);
    count_kernel<<<(E + T - 1) / T, T, 0, s2>>>(ei, E, n);
    dinv_kernel<<<(n + T - 1) / T, T, 0, s2>>>(n);
    scan1_kernel<<<nScanBlocks, SCAN_BLK, 0, s2>>>(n);
    scan2_kernel<<<1, SCAN_BLK, 0, s2>>>(nScanBlocks);
    scan3_kernel<<<nScanBlocks, SCAN_BLK, 0, s2>>>(n);
    fill_kernel<<<(E + T - 1) / T, T, 0, s2>>>(ei, E, n);
    // x @ Wl[0:128]  (Wl rows 0..127 are the x block; row stride OUT_C=32)
    sgemm_kernel<128, 32, 16, 8, 2, 128><<<(n + 127) / 128, 256, 0, s2>>>(x, Wl, pfin, n);

    // main stream: layer-1 GEMM
    sgemm_kernel<128, 64, 16, 8, 4, 128><<<(n + 127) / 128, 256>>>(x, W1, h1pre, n);

    // ---- join
    cudaEventRecord(evJoin, s2);
    cudaStreamWaitEvent(0, evJoin, 0);

    gather1_kernel<<<(n + 7) / 8, 256>>>(b1, n);
    sgemm_kernel<128, 32, 16, 8, 2, 64><<<(n + 127) / 128, 256>>>(agg1, W2, h2pre, n);
    gather2_kernel<<<(n + 7) / 8, 256>>>(b2, n);

    final2_kernel<<<(n + 127) / 128, 256>>>(Wl, bl, out, n);
}